// round 14
// baseline (speedup 1.0000x reference)
#include <cuda_runtime.h>
#include <cuda_fp16.h>
#include <cstdint>

#define N_NODES 32768
#define F_DIM   128
#define C_CH    4
#define H_HEADS 8
#define D_DIM   32
#define DM      256
#define CHN     32          // C*H
#define E_EDGES 65536
#define B_BRIDGE 8192
#define ET      (E_EDGES + 2*B_BRIDGE)   // 81920
#define NW      1280        // total W rows (W_in 256 + W_res 1024)

// ---------------- device scratch (static, no allocation) ----------------
__device__ float g_xl[(size_t)N_NODES * DM];            // 33.5 MB
__device__ float g_exps[(size_t)ET * CHN];              // 10.5 MB
__device__ float g_pe[C_CH * DM];                       //  4 KB
__device__ __half g_xh[(size_t)N_NODES * 128];          // 8.4 MB (X fp16)
__device__ __half g_wh[NW * 128];                       // 328 KB (W fp16 hi)
__device__ __half g_wl[NW * 128];                       // 328 KB (W fp16 lo)
__device__ __half g_res[(size_t)N_NODES * 1024];        // 67 MB (residual fp16)
__device__ int  g_cnt[N_NODES];
__device__ int  g_rowptr[N_NODES + 1];
__device__ int  g_wcur[N_NODES];
__device__ int2 g_epack[ET];            // {edge id, s2 = edge_index[full_src]}

__device__ __forceinline__ uint32_t smem_u32(const void* p) {
    uint32_t a;
    asm("{ .reg .u64 t; cvta.to.shared.u64 t, %1; cvt.u32.u64 %0, t; }"
        : "=r"(a) : "l"(p));
    return a;
}
__device__ __forceinline__ void cp16(uint32_t dst, const void* src) {
    asm volatile("cp.async.ca.shared.global [%0], [%1], 16;"
                 :: "r"(dst), "l"(src) : "memory");
}
__device__ __forceinline__ void ldm_x4(uint32_t* r, uint32_t addr) {
    asm volatile("ldmatrix.sync.aligned.m8n8.x4.shared.b16 {%0,%1,%2,%3}, [%4];"
                 : "=r"(r[0]), "=r"(r[1]), "=r"(r[2]), "=r"(r[3]) : "r"(addr));
}

__device__ __forceinline__ int edge_dst(int e, const int* __restrict__ ei,
                                        const int* __restrict__ bi) {
    if (e < E_EDGES)                 return ei[E_EDGES + e];
    if (e < E_EDGES + B_BRIDGE)      return bi[B_BRIDGE + (e - E_EDGES)];
    return bi[e - E_EDGES - B_BRIDGE];
}

// ---------------- init: zero histogram, compute sinusoidal PE ------------
__global__ void init_kernel() {
    int gid = blockIdx.x * 256 + threadIdx.x;
    if (gid < N_NODES) g_cnt[gid] = 0;
    if (gid < C_CH * DM) {
        int c  = gid >> 8;
        int hd = gid & 255;
        float di  = (float)(hd & ~1);
        float div = powf(10000.f, di / 256.f);
        float ang = (float)c / div;
        g_pe[gid] = (hd & 1) ? cosf(ang) : sinf(ang);
    }
}

// ---------------- CSR build ----------------------------------------------
__global__ void hist_kernel(const int* __restrict__ ei, const int* __restrict__ bi) {
    int e = blockIdx.x * 256 + threadIdx.x;
    if (e < ET) atomicAdd(&g_cnt[edge_dst(e, ei, bi)], 1);
}
__global__ void scan_kernel() {
    __shared__ int sd[1024];
    const int tid = threadIdx.x;
    int loc[32], sum = 0;
    const int base = tid * 32;
    #pragma unroll
    for (int k = 0; k < 32; k++) { loc[k] = g_cnt[base + k]; sum += loc[k]; }
    sd[tid] = sum; __syncthreads();
    for (int off = 1; off < 1024; off <<= 1) {
        int v = (tid >= off) ? sd[tid - off] : 0;
        __syncthreads();
        sd[tid] += v;
        __syncthreads();
    }
    int run = sd[tid] - sum;
    #pragma unroll
    for (int k = 0; k < 32; k++) {
        g_rowptr[base + k] = run;
        g_wcur[base + k]   = run;
        run += loc[k];
    }
    if (tid == 1023) g_rowptr[N_NODES] = run;
}
// fill: CSR slot gets {e, s2} so scatter has no pointer-chase
__global__ void fill_kernel(const int* __restrict__ ei, const int* __restrict__ bi) {
    int e = blockIdx.x * 256 + threadIdx.x;
    if (e < ET) {
        int dst, fs;
        if (e < E_EDGES)                 { dst = ei[E_EDGES + e];                       fs = ei[e]; }
        else if (e < E_EDGES + B_BRIDGE) { int i = e - E_EDGES;
                                           dst = bi[B_BRIDGE + i];                     fs = bi[i]; }
        else                             { int i = e - E_EDGES - B_BRIDGE;
                                           dst = bi[i];                                fs = bi[B_BRIDGE + i]; }
        const int s2 = ei[fs];           // faithful reference bug resolved here
        int pos = atomicAdd(&g_wcur[dst], 1);
        g_epack[pos] = make_int2(e, s2);
    }
}

// ---------------- prep: X -> fp16; W -> fp16 hi/lo ------------------------
#define NX4 ((N_NODES * 128) / 4)
#define NW4 ((NW * 128) / 4)
__global__ void prep_kernel(const float* __restrict__ x,
                            const float* __restrict__ W_in,
                            const float* __restrict__ W_res) {
    int gid = blockIdx.x * 256 + threadIdx.x;
    if (gid < NX4) {
        float4 v = ((const float4*)x)[gid];
        __half2 h0 = __floats2half2_rn(v.x, v.y);
        __half2 h1 = __floats2half2_rn(v.z, v.w);
        ((uint2*)g_xh)[gid] = make_uint2(*(uint32_t*)&h0, *(uint32_t*)&h1);
    } else if (gid < NX4 + NW4) {
        int j   = gid - NX4;
        int row = j >> 5;
        int c   = j & 31;
        const float* src = (row < 256) ? (W_in + (size_t)row * 128)
                                       : (W_res + (size_t)(row - 256) * 128);
        float4 v = ((const float4*)src)[c];
        __half2 h0 = __floats2half2_rn(v.x, v.y);
        __half2 h1 = __floats2half2_rn(v.z, v.w);
        __half2 l0 = __floats2half2_rn(v.x - __half2float(__low2half(h0)),
                                       v.y - __half2float(__high2half(h0)));
        __half2 l1 = __floats2half2_rn(v.z - __half2float(__low2half(h1)),
                                       v.w - __half2float(__high2half(h1)));
        ((uint2*)g_wh)[j] = make_uint2(*(uint32_t*)&h0, *(uint32_t*)&h1);
        ((uint2*)g_wl)[j] = make_uint2(*(uint32_t*)&l0, *(uint32_t*)&l1);
    }
}

// ====== fp16 2-product mma.sync GEMM (X_h*W_h + X_h*W_l), cp.async ========
#define AST2 40
#define TS   (128 * AST2)                 // tile elems (5120)
#define SS3  (3 * TS)                     // stage elems (A, Bh, Bl)
#define GEMM_SMEM (2 * SS3 * 2)           // 61440 B

__device__ __forceinline__ void mma_f16(float* c, const uint32_t* a,
                                        uint32_t b0, uint32_t b1) {
    asm volatile(
        "mma.sync.aligned.m16n8k16.row.col.f32.f16.f16.f32 "
        "{%0,%1,%2,%3}, {%4,%5,%6,%7}, {%8,%9}, {%0,%1,%2,%3};"
        : "+f"(c[0]), "+f"(c[1]), "+f"(c[2]), "+f"(c[3])
        : "r"(a[0]), "r"(a[1]), "r"(a[2]), "r"(a[3]), "r"(b0), "r"(b1));
}

__global__ void __launch_bounds__(256, 2) gemm_mma_kernel(
    const float* __restrict__ bias, int nbase)
{
    extern __shared__ __align__(16) __half smem[];
    const int tid  = threadIdx.x;
    const int wid  = tid >> 5, lane = tid & 31;
    const int wr   = wid & 1;
    const int wc   = wid >> 1;
    const int m0   = blockIdx.y * 128;
    const int nb   = nbase + blockIdx.x;
    const int n0g  = nb * 128;
    const uint32_t sbase = smem_u32(smem);

    const int aIdx = (wr * 64 + (lane & 7) + ((lane >> 3) & 1) * 8) * AST2
                   + ((lane >> 4) & 1) * 8;
    const int bIdx = (wc * 32 + ((lane >> 4) & 1) * 8 + (lane & 7)) * AST2
                   + ((lane >> 3) & 1) * 8;

    float acc[4][4][4];
    #pragma unroll
    for (int a = 0; a < 4; a++)
        #pragma unroll
        for (int b = 0; b < 4; b++)
            #pragma unroll
            for (int cc = 0; cc < 4; cc++) acc[a][b][cc] = 0.f;

    // stage chunk c (K cols kk..kk+31): tiles A(X_h), Bh(W_h), Bl(W_l)
    auto stage = [&](int c, int s) {
        const int kk = c * 32;
        const uint32_t sb = sbase + s * (SS3 * 2);
        #pragma unroll
        for (int r = 0; r < 6; r++) {
            int i = tid + r * 256;            // 1536 cp16 total
            int tile = i >> 9, j = i & 511;
            int row = j >> 2, c4 = j & 3;
            uint32_t doff = sb + tile * (TS * 2) + row * (AST2 * 2) + c4 * 16;
            const __half* src;
            size_t go = (size_t)kk + c4 * 8;
            if      (tile == 0) src = g_xh + (size_t)(m0 + row) * 128 + go;
            else if (tile == 1) src = g_wh + (size_t)(n0g + row) * 128 + go;
            else                src = g_wl + (size_t)(n0g + row) * 128 + go;
            cp16(doff, src);
        }
        asm volatile("cp.async.commit_group;");
    };

    stage(0, 0);
    for (int c = 0; c < 4; c++) {
        if (c > 0) __syncthreads();
        if (c < 3) {
            stage(c + 1, (c + 1) & 1);
            asm volatile("cp.async.wait_group 1;" ::: "memory");
        } else {
            asm volatile("cp.async.wait_group 0;" ::: "memory");
        }
        __syncthreads();

        const uint32_t bufb = sbase + (c & 1) * (SS3 * 2);
        #pragma unroll
        for (int ks = 0; ks < 2; ks++) {
            const int k0 = ks * 16;
            uint32_t ah[4][4], Bh[2][4], Bl[2][4];
            const uint32_t aAddr = bufb + (aIdx + k0) * 2;
            const uint32_t bAddr = bufb + (TS * 2) + (bIdx + k0) * 2;
            #pragma unroll
            for (int mi = 0; mi < 4; mi++)
                ldm_x4(ah[mi], aAddr + mi * (16 * AST2 * 2));
            #pragma unroll
            for (int np = 0; np < 2; np++) {
                ldm_x4(Bh[np], bAddr + np * (16 * AST2 * 2));
                ldm_x4(Bl[np], bAddr + (TS * 2) + np * (16 * AST2 * 2));
            }
            #pragma unroll
            for (int ni = 0; ni < 4; ni++) {
                const int np = ni >> 1, hf = (ni & 1) * 2;
                const uint32_t bh0 = Bh[np][hf], bh1 = Bh[np][hf + 1];
                const uint32_t bl0 = Bl[np][hf], bl1 = Bl[np][hf + 1];
                #pragma unroll
                for (int mi = 0; mi < 4; mi++) {
                    mma_f16(acc[mi][ni], ah[mi], bh0, bh1);
                    mma_f16(acc[mi][ni], ah[mi], bl0, bl1);
                }
            }
        }
    }

    const int mrow = m0 + wr * 64 + (lane >> 2);
    const int ncol = wc * 32 + 2 * (lane & 3);
    #pragma unroll
    for (int mi = 0; mi < 4; mi++) {
        #pragma unroll
        for (int ni = 0; ni < 4; ni++) {
            int m = mrow + mi * 16;
            int nl = ncol + ni * 8;
            float* c = acc[mi][ni];
            if (nb < 2) {
                int col = nb * 128 + nl;
                *(float2*)(g_xl + (size_t)m * 256 + col)       = make_float2(c[0], c[1]);
                *(float2*)(g_xl + (size_t)(m + 8) * 256 + col) = make_float2(c[2], c[3]);
            } else {
                int col = (nb - 2) * 128 + nl;
                float b0 = __ldg(bias + col), b1 = __ldg(bias + col + 1);
                __half2 r0 = __floats2half2_rn(c[0] + b0, c[1] + b1);
                __half2 r1 = __floats2half2_rn(c[2] + b0, c[3] + b1);
                *(uint32_t*)(g_res + (size_t)m * 1024 + col)       = *(uint32_t*)&r0;
                *(uint32_t*)(g_res + (size_t)(m + 8) * 1024 + col) = *(uint32_t*)&r1;
            }
        }
    }
}

// ---------------- scores: one warp per edge, 31-shfl transpose reduce ----
__global__ __launch_bounds__(256) void scores_kernel(
    const int* __restrict__ edge_index, const int* __restrict__ bridge_index,
    const float* __restrict__ double_attn)
{
    __shared__ float pe_s[1024];
    __shared__ float aw_s[1024];
    for (int i = threadIdx.x; i < 1024; i += 256) {
        pe_s[i] = g_pe[i];
        aw_s[i] = double_attn[i];
    }
    __syncthreads();
    const int e    = (blockIdx.x * 256 + threadIdx.x) >> 5;
    const int lane = threadIdx.x & 31;

    int u, v, type;
    if (e < E_EDGES)                { u = edge_index[e];   v = edge_index[E_EDGES + e];   type = 0; }
    else if (e < E_EDGES + B_BRIDGE){ int i = e - E_EDGES;            u = bridge_index[i]; v = bridge_index[B_BRIDGE + i]; type = 1; }
    else                            { int i = e - E_EDGES - B_BRIDGE; u = bridge_index[i]; v = bridge_index[B_BRIDGE + i]; type = 2; }

    const float* xu = g_xl + (size_t)u * DM;
    const float* xv = g_xl + (size_t)v * DM;
    float S[8];
    #pragma unroll
    for (int h = 0; h < 8; h++) S[h] = xu[h * 32 + lane] + xv[h * 32 + lane];

    float vch[32];
    #pragma unroll
    for (int ch = 0; ch < 32; ch++) {
        const int c = ch >> 3, h = ch & 7;
        int c2;
        if (type == 0)      c2 = c;
        else if (type == 1) c2 = (c < 3) ? c + 1 : 3;
        else                c2 = (c > 0) ? c - 1 : 0;
        float t = S[h] + pe_s[c * 256 + h * 32 + lane] + pe_s[c2 * 256 + h * 32 + lane];
        t = (t >= 0.f) ? t : 0.2f * t;
        bool masked = (type == 1 && c == 3) || (type == 2 && c == 0);
        vch[ch] = masked ? 0.f : t * aw_s[ch * 32 + lane];
    }
    #pragma unroll
    for (int off = 16; off; off >>= 1) {
        const bool up = (lane & off) != 0;
        #pragma unroll
        for (int k = 0; k < off; k++) {
            float sent = up ? vch[k] : vch[k + off];
            float recv = __shfl_xor_sync(0xffffffffu, sent, off);
            vch[k] = (up ? vch[k + off] : vch[k]) + recv;
        }
    }
    g_exps[(size_t)e * 32 + lane] = expf(vch[0]);  // max-shift alpha-invariant
}

// --- single-pass scatter + fp16 residual + PReLU -> out (write-only) -----
__global__ void __launch_bounds__(256, 2) scatter_fused_kernel(
    float* __restrict__ out, const float* __restrict__ pw)
{
    __shared__ __align__(16) float pe_s[1024];
    for (int i = threadIdx.x; i < 1024; i += 256) pe_s[i] = g_pe[i];
    __syncthreads();
    const int n    = blockIdx.x * 8 + (threadIdx.x >> 5);
    const int lane = threadIdx.x & 31;
    const int start = g_rowptr[n], end = g_rowptr[n + 1];

    const int q = lane & 7;            // d-quad
    const int g = lane >> 3;           // chain
    float4 accv[8];
    #pragma unroll
    for (int it = 0; it < 8; it++) accv[it] = make_float4(0.f, 0.f, 0.f, 0.f);
    float dsum = 0.f;                  // lane = channel

    int2 p = (start < end) ? g_epack[start] : make_int2(0, 0);
    for (int j = start; j < end; j++) {
        const int2 pn = (j + 1 < end) ? g_epack[j + 1] : p;   // prefetch

        const float ex = g_exps[(size_t)p.x * 32 + lane];     // lane = ch
        const float4* xs = (const float4*)(g_xl + (size_t)p.y * DM);
        float4 xvv[8];
        #pragma unroll
        for (int h = 0; h < 8; h++) xvv[h] = xs[h * 8 + q];

        dsum += ex;
        #pragma unroll
        for (int it = 0; it < 8; it++) {
            const int ch = g * 8 + it;
            const float w = __shfl_sync(0xffffffffu, ex, ch);
            const float4 pe4 = *(const float4*)(pe_s + g * 256 + it * 32 + q * 4);
            accv[it].x += (xvv[it].x + pe4.x) * w;
            accv[it].y += (xvv[it].y + pe4.y) * w;
            accv[it].z += (xvv[it].z + pe4.z) * w;
            accv[it].w += (xvv[it].w + pe4.w) * w;
        }
        p = pn;
    }

    const float inv = 1.f / (dsum + 1e-16f);    // lane = channel
    const float w = pw[0];
    const __half* rb = g_res + (size_t)n * 1024;
    float* ob = out + (size_t)n * 1024;
    #pragma unroll
    for (int it = 0; it < 8; it++) {
        const int ch = g * 8 + it;
        const float ich = __shfl_sync(0xffffffffu, inv, ch);
        const int idx = ch * 32 + q * 4;
        uint2 rr = *(const uint2*)(rb + idx);
        __half2 h01 = *(__half2*)&rr.x;
        __half2 h23 = *(__half2*)&rr.y;
        float4 r;
        r.x = __low2float(h01)  + accv[it].x * ich;
        r.y = __high2float(h01) + accv[it].y * ich;
        r.z = __low2float(h23)  + accv[it].z * ich;
        r.w = __high2float(h23) + accv[it].w * ich;
        r.x = (r.x >= 0.f) ? r.x : w * r.x;
        r.y = (r.y >= 0.f) ? r.y : w * r.y;
        r.z = (r.z >= 0.f) ? r.z : w * r.z;
        r.w = (r.w >= 0.f) ? r.w : w * r.w;
        *(float4*)(ob + idx) = r;
    }
}

// ---------------- launch --------------------------------------------------
extern "C" void kernel_launch(void* const* d_in, const int* in_sizes, int n_in,
                              void* d_out, int out_size) {
    const float* x            = (const float*)d_in[0];
    const int*   edge_index   = (const int*)  d_in[1];
    const int*   bridge_index = (const int*)  d_in[2];
    const float* W_in         = (const float*)d_in[3];
    const float* double_attn  = (const float*)d_in[4];
    const float* W_res        = (const float*)d_in[5];
    const float* bias         = (const float*)d_in[6];
    const float* prelu_w      = (const float*)d_in[7];
    float* out = (float*)d_out;

    cudaFuncSetAttribute(gemm_mma_kernel,
                         cudaFuncAttributeMaxDynamicSharedMemorySize, GEMM_SMEM);

    cudaStream_t s1;
    cudaStreamCreate(&s1);
    cudaEvent_t ev_fork, ev_xl, ev_sc;
    cudaEventCreateWithFlags(&ev_fork, cudaEventDisableTiming);
    cudaEventCreateWithFlags(&ev_xl,   cudaEventDisableTiming);
    cudaEventCreateWithFlags(&ev_sc,   cudaEventDisableTiming);

    // side stream: PE + CSR build (hidden behind prep + GEMM)
    cudaEventRecord(ev_fork, 0);
    cudaStreamWaitEvent(s1, ev_fork, 0);
    init_kernel<<<128, 256, 0, s1>>>();
    hist_kernel<<<ET / 256, 256, 0, s1>>>(edge_index, bridge_index);
    scan_kernel<<<1, 1024, 0, s1>>>();
    fill_kernel<<<ET / 256, 256, 0, s1>>>(edge_index, bridge_index);

    // main stream: prep + xl-GEMM, then residual GEMM (fp16 scratch)
    prep_kernel<<<(NX4 + NW4 + 255) / 256, 256>>>(x, W_in, W_res);
    gemm_mma_kernel<<<dim3(2, 256), 256, GEMM_SMEM>>>(bias, 0);
    cudaEventRecord(ev_xl, 0);
    gemm_mma_kernel<<<dim3(8, 256), 256, GEMM_SMEM>>>(bias, 2);

    // side stream: scores (needs g_xl + PE) overlapped with gemm_res
    cudaStreamWaitEvent(s1, ev_xl, 0);
    scores_kernel<<<ET / 8, 256, 0, s1>>>(edge_index, bridge_index, double_attn);
    cudaEventRecord(ev_sc, s1);

    // join: single-pass scatter, writes out exactly once
    cudaStreamWaitEvent(0, ev_sc, 0);
    scatter_fused_kernel<<<N_NODES / 8, 256>>>(out, prelu_w);
}

// round 15
// speedup vs baseline: 1.2295x; 1.2295x over previous
#include <cuda_runtime.h>
#include <cuda_fp16.h>
#include <cstdint>

#define N_NODES 32768
#define F_DIM   128
#define C_CH    4
#define H_HEADS 8
#define D_DIM   32
#define DM      256
#define CHN     32          // C*H
#define E_EDGES 65536
#define B_BRIDGE 8192
#define ET      (E_EDGES + 2*B_BRIDGE)   // 81920
#define NW      1280        // total W rows (W_in 256 + W_res 1024)

// ---------------- device scratch (static, no allocation) ----------------
__device__ float g_xl[(size_t)N_NODES * DM];            // 33.5 MB
__device__ float g_exps[(size_t)ET * CHN];              // 10.5 MB
__device__ float g_pe[C_CH * DM];                       //  4 KB
__device__ __half g_xh[(size_t)N_NODES * 128];          // 8.4 MB (X fp16)
__device__ __half g_wh[NW * 128];                       // 328 KB (W fp16)
__device__ int  g_cnt[N_NODES];
__device__ int  g_rowptr[N_NODES + 1];
__device__ int  g_wcur[N_NODES];
__device__ int2 g_epack[ET];            // {edge id, s2 = edge_index[full_src]}

__device__ __forceinline__ uint32_t smem_u32(const void* p) {
    uint32_t a;
    asm("{ .reg .u64 t; cvta.to.shared.u64 t, %1; cvt.u32.u64 %0, t; }"
        : "=r"(a) : "l"(p));
    return a;
}
__device__ __forceinline__ void cp16(uint32_t dst, const void* src) {
    asm volatile("cp.async.ca.shared.global [%0], [%1], 16;"
                 :: "r"(dst), "l"(src) : "memory");
}
__device__ __forceinline__ void ldm_x4(uint32_t* r, uint32_t addr) {
    asm volatile("ldmatrix.sync.aligned.m8n8.x4.shared.b16 {%0,%1,%2,%3}, [%4];"
                 : "=r"(r[0]), "=r"(r[1]), "=r"(r[2]), "=r"(r[3]) : "r"(addr));
}

__device__ __forceinline__ int edge_dst(int e, const int* __restrict__ ei,
                                        const int* __restrict__ bi) {
    if (e < E_EDGES)                 return ei[E_EDGES + e];
    if (e < E_EDGES + B_BRIDGE)      return bi[B_BRIDGE + (e - E_EDGES)];
    return bi[e - E_EDGES - B_BRIDGE];
}

// ---------------- init: zero histogram, compute sinusoidal PE ------------
__global__ void init_kernel() {
    int gid = blockIdx.x * 256 + threadIdx.x;
    if (gid < N_NODES) g_cnt[gid] = 0;
    if (gid < C_CH * DM) {
        int c  = gid >> 8;
        int hd = gid & 255;
        float di  = (float)(hd & ~1);
        float div = powf(10000.f, di / 256.f);
        float ang = (float)c / div;
        g_pe[gid] = (hd & 1) ? cosf(ang) : sinf(ang);
    }
}

// ---------------- CSR build ----------------------------------------------
__global__ void hist_kernel(const int* __restrict__ ei, const int* __restrict__ bi) {
    int e = blockIdx.x * 256 + threadIdx.x;
    if (e < ET) atomicAdd(&g_cnt[edge_dst(e, ei, bi)], 1);
}
__global__ void scan_kernel() {
    __shared__ int sd[1024];
    const int tid = threadIdx.x;
    int loc[32], sum = 0;
    const int base = tid * 32;
    #pragma unroll
    for (int k = 0; k < 32; k++) { loc[k] = g_cnt[base + k]; sum += loc[k]; }
    sd[tid] = sum; __syncthreads();
    for (int off = 1; off < 1024; off <<= 1) {
        int v = (tid >= off) ? sd[tid - off] : 0;
        __syncthreads();
        sd[tid] += v;
        __syncthreads();
    }
    int run = sd[tid] - sum;
    #pragma unroll
    for (int k = 0; k < 32; k++) {
        g_rowptr[base + k] = run;
        g_wcur[base + k]   = run;
        run += loc[k];
    }
    if (tid == 1023) g_rowptr[N_NODES] = run;
}
// fill: CSR slot gets {e, s2} so scatter has no pointer-chase
__global__ void fill_kernel(const int* __restrict__ ei, const int* __restrict__ bi) {
    int e = blockIdx.x * 256 + threadIdx.x;
    if (e < ET) {
        int dst, fs;
        if (e < E_EDGES)                 { dst = ei[E_EDGES + e];                       fs = ei[e]; }
        else if (e < E_EDGES + B_BRIDGE) { int i = e - E_EDGES;
                                           dst = bi[B_BRIDGE + i];                     fs = bi[i]; }
        else                             { int i = e - E_EDGES - B_BRIDGE;
                                           dst = bi[i];                                fs = bi[B_BRIDGE + i]; }
        const int s2 = ei[fs];           // faithful reference bug resolved here
        int pos = atomicAdd(&g_wcur[dst], 1);
        g_epack[pos] = make_int2(e, s2);
    }
}

// ---------------- prep: X, W -> fp16 --------------------------------------
#define NX4 ((N_NODES * 128) / 4)
#define NW4 ((NW * 128) / 4)
__global__ void prep_kernel(const float* __restrict__ x,
                            const float* __restrict__ W_in,
                            const float* __restrict__ W_res) {
    int gid = blockIdx.x * 256 + threadIdx.x;
    float4 v;
    __half* dst;
    if (gid < NX4) {
        v = ((const float4*)x)[gid];
        dst = g_xh;
    } else if (gid < NX4 + NW4) {
        int j   = gid - NX4;
        int row = j >> 5;
        int c   = j & 31;
        const float* src = (row < 256) ? (W_in + (size_t)row * 128)
                                       : (W_res + (size_t)(row - 256) * 128);
        v = ((const float4*)src)[c];
        dst = g_wh;
        gid = j;
    } else return;
    __half2 h0 = __floats2half2_rn(v.x, v.y);
    __half2 h1 = __floats2half2_rn(v.z, v.w);
    ((uint2*)dst)[gid] = make_uint2(*(uint32_t*)&h0, *(uint32_t*)&h1);
}

// ====== pure fp16 mma.sync GEMM (X_h * W_h), cp.async + ldmatrix ==========
#define AST2 40
#define TS   (128 * AST2)                 // tile elems (5120)
#define SS2  (2 * TS)                     // stage elems (A, B)
#define GEMM_SMEM (2 * SS2 * 2)           // 40960 B

__device__ __forceinline__ void mma_f16(float* c, const uint32_t* a,
                                        uint32_t b0, uint32_t b1) {
    asm volatile(
        "mma.sync.aligned.m16n8k16.row.col.f32.f16.f16.f32 "
        "{%0,%1,%2,%3}, {%4,%5,%6,%7}, {%8,%9}, {%0,%1,%2,%3};"
        : "+f"(c[0]), "+f"(c[1]), "+f"(c[2]), "+f"(c[3])
        : "r"(a[0]), "r"(a[1]), "r"(a[2]), "r"(a[3]), "r"(b0), "r"(b1));
}

__global__ void __launch_bounds__(256, 2) gemm_mma_kernel(
    const float* __restrict__ bias, float* __restrict__ out, int nbase)
{
    extern __shared__ __align__(16) __half smem[];
    const int tid  = threadIdx.x;
    const int wid  = tid >> 5, lane = tid & 31;
    const int wr   = wid & 1;
    const int wc   = wid >> 1;
    const int m0   = blockIdx.y * 128;
    const int nb   = nbase + blockIdx.x;
    const int n0g  = nb * 128;
    const uint32_t sbase = smem_u32(smem);

    const int aIdx = (wr * 64 + (lane & 7) + ((lane >> 3) & 1) * 8) * AST2
                   + ((lane >> 4) & 1) * 8;
    const int bIdx = (wc * 32 + ((lane >> 4) & 1) * 8 + (lane & 7)) * AST2
                   + ((lane >> 3) & 1) * 8;

    float acc[4][4][4];
    #pragma unroll
    for (int a = 0; a < 4; a++)
        #pragma unroll
        for (int b = 0; b < 4; b++)
            #pragma unroll
            for (int cc = 0; cc < 4; cc++) acc[a][b][cc] = 0.f;

    // stage chunk c (K cols kk..kk+31): tiles A(X_h), B(W_h)
    auto stage = [&](int c, int s) {
        const int kk = c * 32;
        const uint32_t sb = sbase + s * (SS2 * 2);
        #pragma unroll
        for (int r = 0; r < 4; r++) {
            int i = tid + r * 256;            // 1024 cp16 total
            int tile = i >> 9, j = i & 511;
            int row = j >> 2, c4 = j & 3;
            uint32_t doff = sb + tile * (TS * 2) + row * (AST2 * 2) + c4 * 16;
            const __half* src;
            size_t go = (size_t)kk + c4 * 8;
            if (tile == 0) src = g_xh + (size_t)(m0 + row) * 128 + go;
            else           src = g_wh + (size_t)(n0g + row) * 128 + go;
            cp16(doff, src);
        }
        asm volatile("cp.async.commit_group;");
    };

    stage(0, 0);
    for (int c = 0; c < 4; c++) {
        if (c > 0) __syncthreads();
        if (c < 3) {
            stage(c + 1, (c + 1) & 1);
            asm volatile("cp.async.wait_group 1;" ::: "memory");
        } else {
            asm volatile("cp.async.wait_group 0;" ::: "memory");
        }
        __syncthreads();

        const uint32_t bufb = sbase + (c & 1) * (SS2 * 2);
        #pragma unroll
        for (int ks = 0; ks < 2; ks++) {
            const int k0 = ks * 16;
            uint32_t ah[4][4], Bf[2][4];
            const uint32_t aAddr = bufb + (aIdx + k0) * 2;
            const uint32_t bAddr = bufb + (TS * 2) + (bIdx + k0) * 2;
            #pragma unroll
            for (int mi = 0; mi < 4; mi++)
                ldm_x4(ah[mi], aAddr + mi * (16 * AST2 * 2));
            #pragma unroll
            for (int np = 0; np < 2; np++)
                ldm_x4(Bf[np], bAddr + np * (16 * AST2 * 2));
            #pragma unroll
            for (int ni = 0; ni < 4; ni++) {
                const int np = ni >> 1, hf = (ni & 1) * 2;
                const uint32_t b0 = Bf[np][hf], b1 = Bf[np][hf + 1];
                #pragma unroll
                for (int mi = 0; mi < 4; mi++)
                    mma_f16(acc[mi][ni], ah[mi], b0, b1);
            }
        }
    }

    const int mrow = m0 + wr * 64 + (lane >> 2);
    const int ncol = wc * 32 + 2 * (lane & 3);
    #pragma unroll
    for (int mi = 0; mi < 4; mi++) {
        #pragma unroll
        for (int ni = 0; ni < 4; ni++) {
            int m = mrow + mi * 16;
            int nl = ncol + ni * 8;
            float* c = acc[mi][ni];
            if (nb < 2) {
                int col = nb * 128 + nl;
                *(float2*)(g_xl + (size_t)m * 256 + col)       = make_float2(c[0], c[1]);
                *(float2*)(g_xl + (size_t)(m + 8) * 256 + col) = make_float2(c[2], c[3]);
            } else {
                int col = (nb - 2) * 128 + nl;
                float b0 = __ldg(bias + col), b1 = __ldg(bias + col + 1);
                *(float2*)(out + (size_t)m * 1024 + col)       = make_float2(c[0] + b0, c[1] + b1);
                *(float2*)(out + (size_t)(m + 8) * 1024 + col) = make_float2(c[2] + b0, c[3] + b1);
            }
        }
    }
}

// ---------------- scores: one warp per edge, 31-shfl transpose reduce ----
__global__ __launch_bounds__(256) void scores_kernel(
    const int* __restrict__ edge_index, const int* __restrict__ bridge_index,
    const float* __restrict__ double_attn)
{
    __shared__ float pe_s[1024];
    __shared__ float aw_s[1024];
    for (int i = threadIdx.x; i < 1024; i += 256) {
        pe_s[i] = g_pe[i];
        aw_s[i] = double_attn[i];
    }
    __syncthreads();
    const int e    = (blockIdx.x * 256 + threadIdx.x) >> 5;
    const int lane = threadIdx.x & 31;

    int u, v, type;
    if (e < E_EDGES)                { u = edge_index[e];   v = edge_index[E_EDGES + e];   type = 0; }
    else if (e < E_EDGES + B_BRIDGE){ int i = e - E_EDGES;            u = bridge_index[i]; v = bridge_index[B_BRIDGE + i]; type = 1; }
    else                            { int i = e - E_EDGES - B_BRIDGE; u = bridge_index[i]; v = bridge_index[B_BRIDGE + i]; type = 2; }

    const float* xu = g_xl + (size_t)u * DM;
    const float* xv = g_xl + (size_t)v * DM;
    float S[8];
    #pragma unroll
    for (int h = 0; h < 8; h++) S[h] = xu[h * 32 + lane] + xv[h * 32 + lane];

    float vch[32];
    #pragma unroll
    for (int ch = 0; ch < 32; ch++) {
        const int c = ch >> 3, h = ch & 7;
        int c2;
        if (type == 0)      c2 = c;
        else if (type == 1) c2 = (c < 3) ? c + 1 : 3;
        else                c2 = (c > 0) ? c - 1 : 0;
        float t = S[h] + pe_s[c * 256 + h * 32 + lane] + pe_s[c2 * 256 + h * 32 + lane];
        t = (t >= 0.f) ? t : 0.2f * t;
        bool masked = (type == 1 && c == 3) || (type == 2 && c == 0);
        vch[ch] = masked ? 0.f : t * aw_s[ch * 32 + lane];
    }
    #pragma unroll
    for (int off = 16; off; off >>= 1) {
        const bool up = (lane & off) != 0;
        #pragma unroll
        for (int k = 0; k < off; k++) {
            float sent = up ? vch[k] : vch[k + off];
            float recv = __shfl_xor_sync(0xffffffffu, sent, off);
            vch[k] = (up ? vch[k + off] : vch[k]) + recv;
        }
    }
    g_exps[(size_t)e * 32 + lane] = expf(vch[0]);  // max-shift alpha-invariant
}

// ------- single-pass scatter + residual + PReLU (precomputed s2) ---------
__global__ void __launch_bounds__(256, 2) scatter_fused_kernel(
    float* __restrict__ out, const float* __restrict__ pw)
{
    __shared__ __align__(16) float pe_s[1024];
    for (int i = threadIdx.x; i < 1024; i += 256) pe_s[i] = g_pe[i];
    __syncthreads();
    const int n    = blockIdx.x * 8 + (threadIdx.x >> 5);
    const int lane = threadIdx.x & 31;
    const int start = g_rowptr[n], end = g_rowptr[n + 1];

    const int q = lane & 7;            // d-quad
    const int g = lane >> 3;           // chain
    float4 accv[8];
    #pragma unroll
    for (int it = 0; it < 8; it++) accv[it] = make_float4(0.f, 0.f, 0.f, 0.f);
    float dsum = 0.f;                  // lane = channel

    int2 p = (start < end) ? g_epack[start] : make_int2(0, 0);
    for (int j = start; j < end; j++) {
        const int2 pn = (j + 1 < end) ? g_epack[j + 1] : p;   // prefetch

        const float ex = g_exps[(size_t)p.x * 32 + lane];     // lane = ch
        const float4* xs = (const float4*)(g_xl + (size_t)p.y * DM);
        float4 xvv[8];
        #pragma unroll
        for (int h = 0; h < 8; h++) xvv[h] = xs[h * 8 + q];

        dsum += ex;
        #pragma unroll
        for (int it = 0; it < 8; it++) {
            const int ch = g * 8 + it;
            const float w = __shfl_sync(0xffffffffu, ex, ch);
            const float4 pe4 = *(const float4*)(pe_s + g * 256 + it * 32 + q * 4);
            accv[it].x += (xvv[it].x + pe4.x) * w;
            accv[it].y += (xvv[it].y + pe4.y) * w;
            accv[it].z += (xvv[it].z + pe4.z) * w;
            accv[it].w += (xvv[it].w + pe4.w) * w;
        }
        p = pn;
    }

    const float inv = 1.f / (dsum + 1e-16f);    // lane = channel
    const float w = pw[0];
    float* ob = out + (size_t)n * 1024;
    #pragma unroll
    for (int it = 0; it < 8; it++) {
        const int ch = g * 8 + it;
        const float ich = __shfl_sync(0xffffffffu, inv, ch);
        const int idx = ch * 32 + q * 4;
        float4 r = *(const float4*)(ob + idx);
        r.x += accv[it].x * ich;
        r.y += accv[it].y * ich;
        r.z += accv[it].z * ich;
        r.w += accv[it].w * ich;
        r.x = (r.x >= 0.f) ? r.x : w * r.x;
        r.y = (r.y >= 0.f) ? r.y : w * r.y;
        r.z = (r.z >= 0.f) ? r.z : w * r.z;
        r.w = (r.w >= 0.f) ? r.w : w * r.w;
        *(float4*)(ob + idx) = r;
    }
}

// ---------------- launch --------------------------------------------------
extern "C" void kernel_launch(void* const* d_in, const int* in_sizes, int n_in,
                              void* d_out, int out_size) {
    const float* x            = (const float*)d_in[0];
    const int*   edge_index   = (const int*)  d_in[1];
    const int*   bridge_index = (const int*)  d_in[2];
    const float* W_in         = (const float*)d_in[3];
    const float* double_attn  = (const float*)d_in[4];
    const float* W_res        = (const float*)d_in[5];
    const float* bias         = (const float*)d_in[6];
    const float* prelu_w      = (const float*)d_in[7];
    float* out = (float*)d_out;

    cudaFuncSetAttribute(gemm_mma_kernel,
                         cudaFuncAttributeMaxDynamicSharedMemorySize, GEMM_SMEM);

    cudaStream_t s1;
    cudaStreamCreate(&s1);
    cudaEvent_t ev_fork, ev_xl, ev_sc;
    cudaEventCreateWithFlags(&ev_fork, cudaEventDisableTiming);
    cudaEventCreateWithFlags(&ev_xl,   cudaEventDisableTiming);
    cudaEventCreateWithFlags(&ev_sc,   cudaEventDisableTiming);

    // side stream: PE + CSR build (hidden behind prep + GEMM)
    cudaEventRecord(ev_fork, 0);
    cudaStreamWaitEvent(s1, ev_fork, 0);
    init_kernel<<<128, 256, 0, s1>>>();
    hist_kernel<<<ET / 256, 256, 0, s1>>>(edge_index, bridge_index);
    scan_kernel<<<1, 1024, 0, s1>>>();
    fill_kernel<<<ET / 256, 256, 0, s1>>>(edge_index, bridge_index);

    // main stream: prep + xl-GEMM, then residual GEMM (f32 out direct)
    prep_kernel<<<(NX4 + NW4 + 255) / 256, 256>>>(x, W_in, W_res);
    gemm_mma_kernel<<<dim3(2, 256), 256, GEMM_SMEM>>>(bias, out, 0);
    cudaEventRecord(ev_xl, 0);
    gemm_mma_kernel<<<dim3(8, 256), 256, GEMM_SMEM>>>(bias, out, 2);

    // side stream: scores (needs g_xl + PE) overlapped with gemm_res
    cudaStreamWaitEvent(s1, ev_xl, 0);
    scores_kernel<<<ET / 8, 256, 0, s1>>>(edge_index, bridge_index, double_attn);
    cudaEventRecord(ev_sc, s1);

    // join: single-pass scatter
    cudaStreamWaitEvent(0, ev_sc, 0);
    scatter_fused_kernel<<<N_NODES / 8, 256>>>(out, prelu_w);
}